// round 11
// baseline (speedup 1.0000x reference)
#include <cuda_runtime.h>
#include <cuda_bf16.h>
#include <cstdint>

typedef unsigned long long ull;

#define B_SZ 8
#define C_SZ 512
#define H_SZ 56
#define W_SZ 56
#define NHEADS 16
#define DHEAD 32
#define KSZ 7
#define HW_SZ (H_SZ * W_SZ)          // 3136
#define M_TOT (B_SZ * HW_SZ)         // 25088
#define NQKV (3 * C_SZ)              // 1536

// ---------------- device scratch (allocation-guard-safe) ----------------
__device__ float g_qkv[(size_t)M_TOT * NQKV];                 // fp32 q|k|v
__device__ __nv_bfloat16 g_xh[(size_t)M_TOT * C_SZ];
__device__ __nv_bfloat16 g_xl[(size_t)M_TOT * C_SZ];
__device__ __nv_bfloat16 g_wqh[(size_t)NQKV * C_SZ];
__device__ __nv_bfloat16 g_wql[(size_t)NQKV * C_SZ];
__device__ __nv_bfloat16 g_wph[(size_t)C_SZ * C_SZ];
__device__ __nv_bfloat16 g_wpl[(size_t)C_SZ * C_SZ];
__device__ __nv_bfloat16 g_ah[(size_t)M_TOT * C_SZ];
__device__ __nv_bfloat16 g_al[(size_t)M_TOT * C_SZ];

// ---------------- PTX helpers (portable: sm_80+) ----------------
__device__ __forceinline__ uint32_t su32(const void* p) {
    uint32_t a;
    asm("{ .reg .u64 t; cvta.to.shared.u64 t, %1; cvt.u32.u64 %0, t; }" : "=r"(a) : "l"(p));
    return a;
}
__device__ __forceinline__ void cpa16(uint32_t saddr, const void* g) {
    asm volatile("cp.async.cg.shared.global [%0], [%1], 16;\n" :: "r"(saddr), "l"(g));
}
#define CP_COMMIT() asm volatile("cp.async.commit_group;\n" ::: "memory")
#define CP_WAIT1()  asm volatile("cp.async.wait_group 1;\n" ::: "memory")
#define CP_WAIT0()  asm volatile("cp.async.wait_group 0;\n" ::: "memory")

__device__ __forceinline__ void ldsm4(uint32_t* d, uint32_t addr) {
    asm volatile("ldmatrix.sync.aligned.m8n8.x4.shared.b16 {%0,%1,%2,%3}, [%4];"
        : "=r"(d[0]), "=r"(d[1]), "=r"(d[2]), "=r"(d[3]) : "r"(addr));
}
__device__ __forceinline__ void mma_bf16(float* d, const uint32_t* a, const uint32_t* b) {
    asm volatile(
        "mma.sync.aligned.m16n8k16.row.col.f32.bf16.bf16.f32 "
        "{%0,%1,%2,%3}, {%4,%5,%6,%7}, {%8,%9}, {%0,%1,%2,%3};"
        : "+f"(d[0]), "+f"(d[1]), "+f"(d[2]), "+f"(d[3])
        : "r"(a[0]), "r"(a[1]), "r"(a[2]), "r"(a[3]), "r"(b[0]), "r"(b[1]));
}

// =====================================================================
// conv_x: x NCHW fp32 -> NHWC bf16 hi/lo  (32x32 smem transpose tiles)
// =====================================================================
__global__ __launch_bounds__(256)
void conv_x_kernel(const float* __restrict__ x) {
    __shared__ float sm[32][33];
    const int tx = threadIdx.x & 31, ty = threadIdx.x >> 5;
    const int ht = blockIdx.x, ct = blockIdx.y, b = blockIdx.z;
#pragma unroll
    for (int i = 0; i < 4; i++) {
        int cl = ty + i * 8;
        sm[cl][tx] = x[((size_t)b * C_SZ + ct * 32 + cl) * HW_SZ + ht * 32 + tx];
    }
    __syncthreads();
#pragma unroll
    for (int i = 0; i < 4; i++) {
        int rl = ty + i * 8;
        float v = sm[tx][rl];
        __nv_bfloat16 h = __float2bfloat16(v);
        __nv_bfloat16 l = __float2bfloat16(v - __bfloat162float(h));
        size_t idx = (size_t)(b * HW_SZ + ht * 32 + rl) * C_SZ + ct * 32 + tx;
        g_xh[idx] = h;
        g_xl[idx] = l;
    }
}

__global__ void conv_w_kernel(const float* __restrict__ w, __nv_bfloat16* __restrict__ hi,
                              __nv_bfloat16* __restrict__ lo, int n) {
    int i = blockIdx.x * blockDim.x + threadIdx.x;
    if (i < n) {
        float v = w[i];
        __nv_bfloat16 h = __float2bfloat16(v);
        hi[i] = h;
        lo[i] = __float2bfloat16(v - __bfloat162float(h));
    }
}

// =====================================================================
// mma.sync bf16 3-pass split GEMM.  CTA tile 256x128, 16 warps of 64x32,
// 512 threads (4 warps/SMSP), BK=32, 3-stage cp.async ring.
// MODE 0: out[m*ld+n] fp32 (QKV). MODE 1: NCHW + bias (proj).
// =====================================================================
#define BM 256
#define BN 128
#define BKG 32
#define RPAD 40                         // 80B row stride: 16B-aligned, conflict-free
#define ABUF (BM * RPAD * 2)            // 20480 B
#define BBUF (BN * RPAD * 2)            // 10240 B
#define OAh 0
#define OAl ABUF
#define OBh (2 * ABUF)
#define OBl (2 * ABUF + BBUF)
#define STAGEB (2 * ABUF + 2 * BBUF)    // 61440 B
#define NSTAGE 3
#define GEMM_SMEM (NSTAGE * STAGEB)     // 184320 B
#define NTH 512

__device__ __forceinline__ void load_stage(uint32_t sb,
        const __nv_bfloat16* Ah, const __nv_bfloat16* Al,
        const __nv_bfloat16* Bh, const __nv_bfloat16* Bl,
        int kc, int tid) {
    // A: 256 rows x 4 chunks of 16B = 1024 slots
#pragma unroll
    for (int i = 0; i < 2; i++) {
        const int idx = tid + i * NTH;
        const int row = idx >> 2, c4 = idx & 3;
        const size_t g = (size_t)row * 512 + kc * BKG + c4 * 8;
        const uint32_t so = row * (RPAD * 2) + c4 * 16;
        cpa16(sb + OAh + so, Ah + g);
        cpa16(sb + OAl + so, Al + g);
    }
    // B: 128 rows x 4 chunks of 16B = 512 slots
    {
        const int idx = tid;
        const int row = idx >> 2, c4 = idx & 3;
        const size_t g = (size_t)row * 512 + kc * BKG + c4 * 8;
        const uint32_t so = row * (RPAD * 2) + c4 * 16;
        cpa16(sb + OBh + so, Bh + g);
        cpa16(sb + OBl + so, Bl + g);
    }
}

template <int MODE>
__global__ __launch_bounds__(NTH, 1)
void mma_gemm_kernel(const __nv_bfloat16* __restrict__ Ahg, const __nv_bfloat16* __restrict__ Alg,
                     const __nv_bfloat16* __restrict__ Bhg, const __nv_bfloat16* __restrict__ Blg,
                     float* __restrict__ out, const float* __restrict__ bias, int ldout) {
    extern __shared__ __align__(16) char dyn[];
    __shared__ float s_bias[128];

    const int tid = threadIdx.x;
    const int wid = tid >> 5, lane = tid & 31;
    const int wm = wid & 3, wn = wid >> 2;       // 4m x 4n warps; warp tile 64x32
    const int n0 = blockIdx.x * BN;
    const int m0 = blockIdx.y * BM;
    const uint32_t sb = su32(dyn);

    if (MODE == 1 && tid < 128) s_bias[tid] = bias[n0 + tid];

    const __nv_bfloat16* Ah = Ahg + (size_t)m0 * 512;
    const __nv_bfloat16* Al = Alg + (size_t)m0 * 512;
    const __nv_bfloat16* Bh = Bhg + (size_t)n0 * 512;
    const __nv_bfloat16* Bl = Blg + (size_t)n0 * 512;

    float acc[4][4][4];
#pragma unroll
    for (int i = 0; i < 4; i++)
#pragma unroll
        for (int j = 0; j < 4; j++)
#pragma unroll
            for (int e = 0; e < 4; e++) acc[i][j][e] = 0.f;

    load_stage(sb,          Ah, Al, Bh, Bl, 0, tid); CP_COMMIT();
    load_stage(sb + STAGEB, Ah, Al, Bh, Bl, 1, tid); CP_COMMIT();

    const int r8 = lane & 7, sel = lane >> 3;
    const uint32_t a_row_off = (uint32_t)((wm * 64 + (sel & 1) * 8 + r8) * (RPAD * 2));
    const uint32_t a_col_off = (uint32_t)(((sel >> 1) * 8) * 2);
    const uint32_t b_row_off = (uint32_t)((wn * 32 + ((sel >> 1) & 1) * 8 + r8) * (RPAD * 2));
    const uint32_t b_col_off = (uint32_t)(((sel & 1) * 8) * 2);

    const int NKT = 512 / BKG;   // 16
#pragma unroll 1
    for (int kt = 0; kt < NKT; kt++) {
        if (kt < NKT - 1) CP_WAIT1(); else CP_WAIT0();
        __syncthreads();
        if (kt + 2 < NKT) {
            load_stage(sb + ((kt + 2) % NSTAGE) * STAGEB, Ah, Al, Bh, Bl, kt + 2, tid);
            CP_COMMIT();
        }
        const uint32_t st = sb + (kt % NSTAGE) * STAGEB;
#pragma unroll
        for (int ks = 0; ks < 2; ks++) {
            const uint32_t k0b = (uint32_t)(ks * 16 * 2);
            uint32_t fAh[4][4], fAl[4][4], fBh[2][4], fBl[2][4];
#pragma unroll
            for (int im = 0; im < 4; im++) {
                const uint32_t ao = a_row_off + im * 16 * (RPAD * 2) + k0b + a_col_off;
                ldsm4(fAh[im], st + OAh + ao);
                ldsm4(fAl[im], st + OAl + ao);
            }
#pragma unroll
            for (int j2 = 0; j2 < 2; j2++) {
                const uint32_t bo = b_row_off + j2 * 16 * (RPAD * 2) + k0b + b_col_off;
                ldsm4(fBh[j2], st + OBh + bo);
                ldsm4(fBl[j2], st + OBl + bo);
            }
#pragma unroll
            for (int im = 0; im < 4; im++)
#pragma unroll
                for (int jn = 0; jn < 4; jn++)
                    mma_bf16(acc[im][jn], fAh[im], &fBh[jn >> 1][(jn & 1) * 2]);
#pragma unroll
            for (int im = 0; im < 4; im++)
#pragma unroll
                for (int jn = 0; jn < 4; jn++)
                    mma_bf16(acc[im][jn], fAl[im], &fBh[jn >> 1][(jn & 1) * 2]);
#pragma unroll
            for (int im = 0; im < 4; im++)
#pragma unroll
                for (int jn = 0; jn < 4; jn++)
                    mma_bf16(acc[im][jn], fAh[im], &fBl[jn >> 1][(jn & 1) * 2]);
        }
    }

    // epilogue
    const int gid = lane >> 2, tq = lane & 3;
#pragma unroll
    for (int im = 0; im < 4; im++) {
#pragma unroll
        for (int jn = 0; jn < 4; jn++) {
            const int nl = wn * 32 + jn * 8 + 2 * tq;
            const int n = n0 + nl;
            const int m = m0 + wm * 64 + im * 16 + gid;
            if (MODE == 0) {
                float2 v0 = make_float2(acc[im][jn][0], acc[im][jn][1]);
                float2 v1 = make_float2(acc[im][jn][2], acc[im][jn][3]);
                *(float2*)(out + (size_t)m * ldout + n) = v0;
                *(float2*)(out + (size_t)(m + 8) * ldout + n) = v1;
            } else {
                const float b0 = s_bias[nl], b1 = s_bias[nl + 1];
                int bq = m / HW_SZ, hw = m - bq * HW_SZ;
                out[((size_t)bq * C_SZ + n) * HW_SZ + hw]     = acc[im][jn][0] + b0;
                out[((size_t)bq * C_SZ + n + 1) * HW_SZ + hw] = acc[im][jn][1] + b1;
                int m2 = m + 8;
                int bq2 = m2 / HW_SZ, hw2 = m2 - bq2 * HW_SZ;
                out[((size_t)bq2 * C_SZ + n) * HW_SZ + hw2]     = acc[im][jn][2] + b0;
                out[((size_t)bq2 * C_SZ + n + 1) * HW_SZ + hw2] = acc[im][jn][3] + b1;
            }
        }
    }
}

// =====================================================================
// natten: block = (b, head, 8x8 pixel tile); writes bf16 hi/lo att output
// Non-online softmax (logits bounded) — 1 exp2/iter.
// =====================================================================
#define TPOS 196
#define KST 36
#define NAT_SMEM ((2 * TPOS * KST + 169) * 4)

__global__ __launch_bounds__(256)
void natten_kernel(const float* __restrict__ rpb) {
    extern __shared__ __align__(16) float sm[];
    float* ks = sm;
    float* vs = sm + TPOS * KST;
    float* rs = sm + 2 * TPOS * KST;
    const int tid = threadIdx.x;
    const int tile = blockIdx.x;
    const int head = blockIdx.y;
    const int bb = blockIdx.z;
    const int ti = (tile / 7) * 8, tj = (tile % 7) * 8;
    const int rlo = min(max(ti - 3, 0), H_SZ - 14);
    const int clo = min(max(tj - 3, 0), W_SZ - 14);

    for (int idx = tid; idx < TPOS * 8; idx += 256) {
        int pos = idx >> 3, f = idx & 7;
        int pr = pos / 14;
        int pc = pos - pr * 14;
        size_t mm = ((size_t)(bb * HW_SZ + (rlo + pr) * W_SZ + (clo + pc))) * NQKV
                    + C_SZ + head * DHEAD + f * 4;
        *(float4*)&ks[pos * KST + f * 4] = *(const float4*)&g_qkv[mm];
        *(float4*)&vs[pos * KST + f * 4] = *(const float4*)&g_qkv[mm + C_SZ];
    }
    for (int idx = tid; idx < 169; idx += 256) rs[idx] = rpb[head * 169 + idx];

    const int qd = tid & 3, p = tid >> 2;
    const int pi = p >> 3, pj = p & 7;
    const int i = ti + pi, j = tj + pj;
    const size_t mp = (size_t)(bb * HW_SZ + i * W_SZ + j);
    const float scale = 0.17677669529663687f;
    float4 q0 = *(const float4*)&g_qkv[mp * NQKV + head * DHEAD + qd * 8];
    float4 q1 = *(const float4*)&g_qkv[mp * NQKV + head * DHEAD + qd * 8 + 4];
    q0.x *= scale; q0.y *= scale; q0.z *= scale; q0.w *= scale;
    q1.x *= scale; q1.y *= scale; q1.z *= scale; q1.w *= scale;
    __syncthreads();

    const int si = min(max(i - 3, 0), H_SZ - KSZ);
    const int sj = min(max(j - 3, 0), W_SZ - KSZ);
    const int pr0 = (si - rlo) * 14 + (sj - clo);
    const int br0 = (si - i + 6) * 13 + (sj - j + 6);
    const float L2E = 1.4426950408889634f;
    float ssum = 0.f;
    float acc[8];
#pragma unroll
    for (int e = 0; e < 8; e++) acc[e] = 0.f;

#pragma unroll 1
    for (int a = 0; a < KSZ; a++) {
#pragma unroll
        for (int c = 0; c < KSZ; c++) {
            const int off = (pr0 + a * 14 + c) * KST + qd * 8;
            float4 k0 = *(const float4*)&ks[off];
            float4 k1 = *(const float4*)&ks[off + 4];
            float dot = q0.x * k0.x + q0.y * k0.y + q0.z * k0.z + q0.w * k0.w
                      + q1.x * k1.x + q1.y * k1.y + q1.z * k1.z + q1.w * k1.w;
            dot += __shfl_xor_sync(0xffffffffu, dot, 1);
            dot += __shfl_xor_sync(0xffffffffu, dot, 2);
            const float l = dot + rs[br0 + a * 13 + c];
            const float pw = exp2f(l * L2E);
            ssum += pw;
            float4 v0 = *(const float4*)&vs[off];
            float4 v1 = *(const float4*)&vs[off + 4];
            acc[0] += pw * v0.x;
            acc[1] += pw * v0.y;
            acc[2] += pw * v0.z;
            acc[3] += pw * v0.w;
            acc[4] += pw * v1.x;
            acc[5] += pw * v1.y;
            acc[6] += pw * v1.z;
            acc[7] += pw * v1.w;
        }
    }
    const float inv = 1.0f / ssum;
    __align__(16) __nv_bfloat16 hb[8];
    __align__(16) __nv_bfloat16 lb[8];
#pragma unroll
    for (int e = 0; e < 8; e++) {
        float o = acc[e] * inv;
        __nv_bfloat16 h = __float2bfloat16(o);
        hb[e] = h;
        lb[e] = __float2bfloat16(o - __bfloat162float(h));
    }
    const size_t ob = mp * C_SZ + head * DHEAD + qd * 8;
    *(uint4*)&g_ah[ob] = *(const uint4*)hb;
    *(uint4*)&g_al[ob] = *(const uint4*)lb;
}

// =====================================================================
extern "C" void kernel_launch(void* const* d_in, const int* in_sizes, int n_in,
                              void* d_out, int out_size) {
    const float* x      = (const float*)d_in[0];
    const float* qkv_w  = (const float*)d_in[1];
    const float* rpb    = (const float*)d_in[2];
    const float* proj_w = (const float*)d_in[3];
    const float* proj_b = (const float*)d_in[4];
    float* y = (float*)d_out;

    cudaFuncSetAttribute(mma_gemm_kernel<0>, cudaFuncAttributeMaxDynamicSharedMemorySize, GEMM_SMEM);
    cudaFuncSetAttribute(mma_gemm_kernel<1>, cudaFuncAttributeMaxDynamicSharedMemorySize, GEMM_SMEM);
    cudaFuncSetAttribute(natten_kernel, cudaFuncAttributeMaxDynamicSharedMemorySize, NAT_SMEM);

    __nv_bfloat16 *xh, *xl, *wqh, *wql, *wph, *wpl, *ah, *al;
    cudaGetSymbolAddress((void**)&xh,  g_xh);
    cudaGetSymbolAddress((void**)&xl,  g_xl);
    cudaGetSymbolAddress((void**)&wqh, g_wqh);
    cudaGetSymbolAddress((void**)&wql, g_wql);
    cudaGetSymbolAddress((void**)&wph, g_wph);
    cudaGetSymbolAddress((void**)&wpl, g_wpl);
    cudaGetSymbolAddress((void**)&ah,  g_ah);
    cudaGetSymbolAddress((void**)&al,  g_al);
    float* qkv;
    cudaGetSymbolAddress((void**)&qkv, g_qkv);

    conv_x_kernel<<<dim3(HW_SZ / 32, C_SZ / 32, B_SZ), 256>>>(x);
    conv_w_kernel<<<(NQKV * C_SZ + 255) / 256, 256>>>(qkv_w, wqh, wql, NQKV * C_SZ);
    conv_w_kernel<<<(C_SZ * C_SZ + 255) / 256, 256>>>(proj_w, wph, wpl, C_SZ * C_SZ);

    mma_gemm_kernel<0><<<dim3(NQKV / BN, M_TOT / BM), NTH, GEMM_SMEM>>>(
        xh, xl, wqh, wql, qkv, nullptr, NQKV);

    natten_kernel<<<dim3(49, NHEADS, B_SZ), 256, NAT_SMEM>>>(rpb);

    mma_gemm_kernel<1><<<dim3(C_SZ / BN, M_TOT / BM), NTH, GEMM_SMEM>>>(
        ah, al, wph, wpl, y, proj_b, 0);
}